// round 12
// baseline (speedup 1.0000x reference)
#include <cuda_runtime.h>
#include <stdint.h>
#include <math.h>

// Problem constants
#define T_   4096
#define D_   128
#define H_   512
#define H3_  1536
#define WN_  4

#define GC   64       // CTAs in sequential kernel
#define NT   256      // threads per CTA
#define NC   8        // columns owned per CTA (GC*NC = 512)

// ---------------- device scratch ----------------
__device__ float    g_XW [T_ * H3_];          //  25 MB : x@W + b
__device__ float    g_XWa[T_ * H_];           //   8 MB : x@Wa + ba
__device__ float    g_GWx[T_ * WN_ * H3_];    // 100 MB : emb[wid]@Ww + bw
__device__ float    g_cwt[(size_t)T_ * 2048]; //  32 MB : per-step c_w (write-once)
__device__ unsigned g_meta[T_];               // nact(3b) + [w(2b)|d(5b)] x4
__device__ unsigned g_flag[GC * 32];          // spread barrier flags (128B apart)

// ---------------- acquire/release flag ops ----------------
__device__ __forceinline__ unsigned ld_acq(const unsigned* p) {
    unsigned v;
    asm volatile("ld.acquire.gpu.global.u32 %0, [%1];" : "=r"(v) : "l"(p) : "memory");
    return v;
}
__device__ __forceinline__ void st_rel(unsigned* p, unsigned v) {
    asm volatile("st.release.gpu.global.u32 [%0], %1;" :: "l"(p), "r"(v) : "memory");
}

// ---------------- fast transcendentals (validated rel_err 3.5e-7) ----------------
__device__ __forceinline__ float fsig(float x) { return 1.0f / (1.0f + __expf(-x)); }
__device__ __forceinline__ float ftan(float x) {
    float ax = fabsf(x);
    float e  = __expf(-2.0f * ax);
    float t  = (1.0f - e) / (1.0f + e);
    return copysignf(t, x);
}

// ---------------- prep: flag reset + mask dtype detect + meta encode ----------------
__global__ void k_prep(const unsigned* __restrict__ mask32,
                       const void* __restrict__ mask,
                       const int*  __restrict__ wstarts)
{
    __shared__ int sflags;
    int tid = threadIdx.x;
    if (tid == 0) sflags = 7;
    for (int i = tid; i < GC * 32; i += 1024) g_flag[i] = 0;
    __syncthreads();
    int bad = 0;
    for (int i = tid; i < 4096; i += 1024) {
        unsigned w = mask32[i];
        if (w > 1u)                      bad |= 1;   // not int32 0/1
        if (w != 0u && w != 0x3F800000u) bad |= 2;   // not float32 0/1
        if (w & 0xFEFEFEFEu)             bad |= 4;   // not uint8 0/1
    }
    if (bad) atomicAnd(&sflags, ~bad);
    __syncthreads();
    int flags = sflags;
    int mode = (flags & 1) ? 0 : ((flags & 2) ? 1 : 2);
    for (int t = tid; t < T_; t += 1024) {
        unsigned m = 0;
        int nact = 0;
        #pragma unroll
        for (int w = 0; w < WN_; ++w) {
            int i = t * WN_ + w;
            int on = (mode == 0) ? (((const int*)mask)[i] != 0)
                   : (mode == 1) ? (((const float*)mask)[i] != 0.0f)
                                 : (((const unsigned char*)mask)[i] != 0);
            if (on) {
                int d = t - wstarts[i];
                if (d < 1) d = 1;
                if (d > 31) d = 31;
                m |= (unsigned)(w | (d << 2)) << (3 + 7 * nact);
                ++nact;
            }
        }
        g_meta[t] = m | (unsigned)nact;
    }
}

// ---------------- precompute GEMM ----------------
__global__ __launch_bounds__(256) void k_gemm(
    const float* __restrict__ A, const int* __restrict__ gidx,
    const float* __restrict__ Bm, const float* __restrict__ bias,
    const float* __restrict__ B2, const float* __restrict__ bias2,
    int M, int K, int sel)
{
    float* C; int N, bn;
    const float* B  = Bm;
    const float* bs = bias;
    if (sel == 2) { C = g_GWx; N = H3_; bn = blockIdx.x * 64; }
    else {
        if (blockIdx.x < 24) { C = g_XW;  N = H3_; bn = blockIdx.x * 64; }
        else { C = g_XWa; N = H_; bn = (blockIdx.x - 24) * 64; B = B2; bs = bias2; }
    }

    __shared__ float As[16 * 130];
    __shared__ float Bs[16 * 64];

    int tid = threadIdx.x;
    int bm = blockIdx.y * 128;
    int tx = tid & 15;
    int ty = tid >> 4;

    float acc[8][4];
    #pragma unroll
    for (int i = 0; i < 8; ++i)
        #pragma unroll
        for (int j = 0; j < 4; ++j) acc[i][j] = 0.0f;

    for (int k0 = 0; k0 < K; k0 += 16) {
        #pragma unroll
        for (int i = 0; i < 2; ++i) {
            int f = tid + i * 256;
            int row = f >> 2, kq = (f & 3) * 4;
            int ar = gidx ? gidx[bm + row] : (bm + row);
            float4 v = *(const float4*)(A + (size_t)ar * K + k0 + kq);
            As[(kq + 0) * 130 + row] = v.x;
            As[(kq + 1) * 130 + row] = v.y;
            As[(kq + 2) * 130 + row] = v.z;
            As[(kq + 3) * 130 + row] = v.w;
        }
        {
            int row = tid >> 4, cq = (tid & 15) * 4;
            float4 v = *(const float4*)(B + (size_t)(k0 + row) * N + bn + cq);
            *(float4*)&Bs[row * 64 + cq] = v;
        }
        __syncthreads();
        #pragma unroll
        for (int kk = 0; kk < 16; ++kk) {
            float a[8], b[4];
            #pragma unroll
            for (int i = 0; i < 8; ++i) a[i] = As[kk * 130 + ty + i * 16];
            #pragma unroll
            for (int j = 0; j < 4; ++j) b[j] = Bs[kk * 64 + tx + j * 16];
            #pragma unroll
            for (int i = 0; i < 8; ++i)
                #pragma unroll
                for (int j = 0; j < 4; ++j) acc[i][j] += a[i] * b[j];
        }
        __syncthreads();
    }
    #pragma unroll
    for (int i = 0; i < 8; ++i) {
        int m = bm + ty + i * 16;
        #pragma unroll
        for (int j = 0; j < 4; ++j) {
            int n = bn + tx + j * 16;
            C[(size_t)m * N + n] = acc[i][j] + bs[n];
        }
    }
}

// ---------------- smem layout (float offsets) ----------------
// U/UW slices: per (gate,k): 2 float4 (8 cols).  UA: per k: 2 float4.
#define SM_U     0                    // 12288
#define SM_UW    12288                // 12288
#define SM_UA    24576                // 4096
#define SM_RB    28672                // 24 (3 gates x 8 cols), pad to 32
#define SM_RAL   28704                // 32 (4 words x 8 cols)
#define SM_RASH  28736                // 96 : d==1 word dots (step t)
#define SM_RASH2 28832                // 96 : shadow word dots (step t+1)
#define SM_CWO   28928                // 64 ([2 parity][4 words][8 cols])
#define SM_CPRV  28992                // 8
#define SM_CSSH  29000                // 32 (4 words x 8 cols)
#define SM_META  29032                // 4096
#define SM_TOTF  (SM_META + 4096)
#define SMEM_BYTES (SM_TOTF * 4)

// 8-col warp dot: weights float4[k*2+h] smem, state float[512] global,
// bias 8 floats global (lane0 preloads); lane0 stores result(+bias) to dst.
__device__ __forceinline__ void dot8(const float4* __restrict__ w,
                                     const float*  __restrict__ gh,
                                     const float*  __restrict__ gb,
                                     float* __restrict__ dst, int lane) {
    float4 b0 = make_float4(0,0,0,0), b1 = b0;
    if (lane == 0) { b0 = *(const float4*)gb; b1 = *(const float4*)(gb + 4); }
    float a[8];
    #pragma unroll
    for (int i = 0; i < 8; ++i) a[i] = 0.f;
    #pragma unroll
    for (int i = 0; i < 16; ++i) {
        int k = i * 32 + lane;
        float  hh = gh[k];
        float4 w0 = w[k * 2], w1 = w[k * 2 + 1];
        a[0] += w0.x * hh; a[1] += w0.y * hh; a[2] += w0.z * hh; a[3] += w0.w * hh;
        a[4] += w1.x * hh; a[5] += w1.y * hh; a[6] += w1.z * hh; a[7] += w1.w * hh;
    }
    #pragma unroll
    for (int o = 16; o > 0; o >>= 1)
        #pragma unroll
        for (int i = 0; i < 8; ++i) a[i] += __shfl_xor_sync(0xFFFFFFFFu, a[i], o);
    if (lane == 0) {
        dst[0] = a[0] + b0.x; dst[1] = a[1] + b0.y;
        dst[2] = a[2] + b0.z; dst[3] = a[3] + b0.w;
        dst[4] = a[4] + b1.x; dst[5] = a[5] + b1.y;
        dst[6] = a[6] + b1.z; dst[7] = a[7] + b1.w;
    }
}

// fused 24-col word dot: 3 gates (f,i,g) x 8 cols share one row load stream.
__device__ __forceinline__ void dot24(const float4* __restrict__ w,
                                      const float*  __restrict__ gh,
                                      const float*  __restrict__ gb,
                                      float* __restrict__ dst, int lane) {
    float4 b[6];
    #pragma unroll
    for (int i = 0; i < 6; ++i) b[i] = make_float4(0,0,0,0);
    if (lane == 0) {
        #pragma unroll
        for (int g = 0; g < 3; ++g) {
            b[g*2]   = *(const float4*)(gb + g * 512);
            b[g*2+1] = *(const float4*)(gb + g * 512 + 4);
        }
    }
    float a[24];
    #pragma unroll
    for (int i = 0; i < 24; ++i) a[i] = 0.f;
    #pragma unroll
    for (int i = 0; i < 16; ++i) {
        int k = i * 32 + lane;
        float hh = gh[k];
        #pragma unroll
        for (int g = 0; g < 3; ++g) {
            float4 w0 = w[(g * 512 + k) * 2], w1 = w[(g * 512 + k) * 2 + 1];
            a[g*8+0] += w0.x*hh; a[g*8+1] += w0.y*hh;
            a[g*8+2] += w0.z*hh; a[g*8+3] += w0.w*hh;
            a[g*8+4] += w1.x*hh; a[g*8+5] += w1.y*hh;
            a[g*8+6] += w1.z*hh; a[g*8+7] += w1.w*hh;
        }
    }
    #pragma unroll
    for (int o = 16; o > 0; o >>= 1)
        #pragma unroll
        for (int i = 0; i < 24; ++i) a[i] += __shfl_xor_sync(0xFFFFFFFFu, a[i], o);
    if (lane == 0) {
        #pragma unroll
        for (int g = 0; g < 3; ++g) {
            dst[g*8+0] = a[g*8+0] + b[g*2].x;   dst[g*8+1] = a[g*8+1] + b[g*2].y;
            dst[g*8+2] = a[g*8+2] + b[g*2].z;   dst[g*8+3] = a[g*8+3] + b[g*2].w;
            dst[g*8+4] = a[g*8+4] + b[g*2+1].x; dst[g*8+5] = a[g*8+5] + b[g*2+1].y;
            dst[g*8+6] = a[g*8+6] + b[g*2+1].z; dst[g*8+7] = a[g*8+7] + b[g*2+1].w;
        }
    }
}

__global__ __launch_bounds__(NT, 1) void k_seq(
    float* __restrict__ out,                 // [T, 1024] = hidden|cell
    const float* __restrict__ U,
    const float* __restrict__ Uw,
    const float* __restrict__ Ua,
    const float* __restrict__ h0,
    const float* __restrict__ c0)
{
    extern __shared__ float sm[];
    unsigned* s_meta = (unsigned*)(sm + SM_META);
    float4* U8  = (float4*)(sm + SM_U);    // [(gate*512+k)*2 + h]
    float4* UW8 = (float4*)(sm + SM_UW);
    float4* UA8 = (float4*)(sm + SM_UA);   // [k*2 + h]

    const int c     = blockIdx.x;
    const int tid   = threadIdx.x;
    const int jbase = NC * c;
    const int warp  = tid >> 5, lane = tid & 31;

    // ---- one-time: weight column slices + meta table ----
    for (int idx = tid; idx < 3 * 512; idx += NT) {
        int gate = idx >> 9, k = idx & 511;
        const float* pU  = U  + (size_t)k * H3_ + gate * 512 + jbase;
        const float* pUw = Uw + (size_t)k * H3_ + gate * 512 + jbase;
        U8 [idx * 2]     = *(const float4*)pU;
        U8 [idx * 2 + 1] = *(const float4*)(pU + 4);
        UW8[idx * 2]     = *(const float4*)pUw;
        UW8[idx * 2 + 1] = *(const float4*)(pUw + 4);
    }
    for (int k = tid; k < 512; k += NT) {
        const float* pUa = Ua + (size_t)k * H_ + jbase;
        UA8[k * 2]     = *(const float4*)pUa;
        UA8[k * 2 + 1] = *(const float4*)(pUa + 4);
    }
    for (int i = tid; i < T_; i += NT) s_meta[i] = g_meta[i];
    __syncthreads();

    unsigned seq = 0;
    unsigned* myflag = &g_flag[c * 32];

    for (int t = 0; t < T_; ++t) {
        const unsigned meta = s_meta[t];
        const int nact = (int)(meta & 7u);
        const unsigned mN = (t + 1 < T_) ? s_meta[t + 1] : 0u;
        const int nactN = (int)(mN & 7u);

        int wT[4], dT[4], wN[4], dN[4];
        #pragma unroll
        for (int i = 0; i < 4; ++i) {
            unsigned f = meta >> (3 + 7 * i);
            wT[i] = (int)(f & 3u); dT[i] = (int)((f >> 2) & 31u);
            unsigned g = mN >> (3 + 7 * i);
            wN[i] = (int)(g & 3u); dN[i] = (int)((g >> 2) & 31u);
        }
        bool lateT = false;
        for (int i = 0; i < nact; ++i) lateT |= (dT[i] == 1);

        const float* rowHprev = t ? (out + (size_t)(t - 1) * 1024) : h0;
        const float* rowCprev = t ? (out + (size_t)(t - 1) * 1024 + 512) : c0;

        // ======== round 1: everything that depends only on rows <= t-1 ========
        // [0,3): gate dots      [3,3+nact): alpha dots (d>=2 words only)
        // [3+nact, +nact): fused d==1 word dots (late steps)   -> SM_RASH
        // [.., +nactN): fused shadow word dots for t+1 (d>=2)  -> SM_RASH2
        // [last]: micro loads (c_prev, shadow c_s)
        const int base_d1 = 3 + nact;
        const int base_sh = base_d1 + (lateT ? nact : 0);
        const int ntasks  = base_sh + nactN + 1;
        for (int tk = warp; tk < ntasks; tk += 8) {
            if (tk < 3) {
                dot8(U8 + (size_t)tk * 1024, rowHprev,
                     g_XW + (size_t)t * H3_ + tk * 512 + jbase,
                     sm + SM_RB + tk * 8, lane);
            } else if (tk < base_d1) {
                int wi = tk - 3;
                if (dT[wi] >= 2)
                    dot8(UA8, g_cwt + (size_t)t * 2048 + wi * 512,
                         g_XWa + (size_t)t * H_ + jbase,
                         sm + SM_RAL + wi * 8, lane);
            } else if (tk < base_sh) {
                int wi = tk - base_d1;
                if (dT[wi] == 1)
                    dot24(UW8, rowHprev,
                          g_GWx + ((size_t)t * WN_ + wT[wi]) * H3_ + jbase,
                          sm + SM_RASH + wi * 24, lane);
            } else if (tk < base_sh + nactN) {
                int wi = tk - base_sh;
                if (dN[wi] >= 2)
                    dot24(UW8, out + (size_t)(t + 1 - dN[wi]) * 1024,
                          g_GWx + ((size_t)(t + 1) * WN_ + wN[wi]) * H3_ + jbase,
                          sm + SM_RASH2 + wi * 24, lane);
            } else {
                if (lane < 2)
                    ((float4*)(sm + SM_CPRV))[lane] =
                        *(const float4*)(rowCprev + jbase + lane * 4);
                else if (lane < 10) {
                    int q = lane - 2, wi = q >> 1, h = q & 1;
                    if (wi < nactN && dN[wi] >= 2)
                        ((float4*)(sm + SM_CSSH))[wi * 2 + h] = *(const float4*)(
                            out + (size_t)(t + 1 - dN[wi]) * 1024 + 512 + jbase + h * 4);
                }
            }
        }
        __syncthreads();

        // ======== late mid-barrier: publish d==1 c_w(t), then d==1 alphas ======
        if (lateT) {
            ++seq;
            if (warp == 0) {
                if (lane >= 8 && lane < 16) {
                    int q = lane - 8, wi = q >> 1, h = q & 1;
                    if (wi < nact && dT[wi] == 1) {
                        int cb = h * 4;
                        float cw[4];
                        #pragma unroll
                        for (int u = 0; u < 4; ++u) {
                            float fv = sm[SM_RASH + wi * 24 + 0  + cb + u];
                            float iv = sm[SM_RASH + wi * 24 + 8  + cb + u];
                            float gv = sm[SM_RASH + wi * 24 + 16 + cb + u];
                            float cs = sm[SM_CPRV + cb + u];
                            cw[u] = fsig(fv) * cs + fsig(iv) * ftan(gv);
                            sm[SM_CWO + (t & 1) * 32 + wi * 8 + cb + u] = cw[u];
                        }
                        *(float4*)(g_cwt + (size_t)t * 2048 + wi * 512 + jbase + cb) =
                            make_float4(cw[0], cw[1], cw[2], cw[3]);
                    }
                }
                __syncwarp();
                if (lane == 0) st_rel(myflag, seq);
            }
            if (tid < GC) { while (ld_acq(&g_flag[tid * 32]) < seq) {} }
            __syncthreads();
            // d==1 alpha dots
            for (int wi = warp; wi < nact; wi += 8) {
                if (dT[wi] == 1)
                    dot8(UA8, g_cwt + (size_t)t * 2048 + wi * 512,
                         g_XWa + (size_t)t * H_ + jbase,
                         sm + SM_RAL + wi * 8, lane);
            }
            __syncthreads();
        }

        // ======== finalize (warp 0): combine lanes 0-7, shadow cw lanes 8-15 ====
        ++seq;
        if (warp == 0) {
            if (lane < 8) {
                int jl = lane;
                float ig = fsig(sm[SM_RB + 0  + jl]);
                float og = fsig(sm[SM_RB + 8  + jl]);
                float gt = ftan(sm[SM_RB + 16 + jl]);
                float c1;
                if (nact) {
                    float den = __expf(ig), num = den * gt;
                    for (int wi = 0; wi < nact; ++wi) {
                        float al = sm[SM_RAL + wi * 8 + jl];
                        float cw = sm[SM_CWO + (t & 1) * 32 + wi * 8 + jl];
                        float e  = __expf(fsig(al));
                        den += e; num += e * cw;
                    }
                    c1 = num / den;
                } else {
                    float cp = sm[SM_CPRV + jl];
                    c1 = (1.0f - ig) * cp + ig * gt;
                }
                float h1 = og * ftan(c1);
                out[(size_t)t * 1024 + jbase + jl]       = h1;
                out[(size_t)t * 1024 + 512 + jbase + jl] = c1;
            } else if (lane < 16) {
                int q = lane - 8, wi = q >> 1, h = q & 1;
                if (wi < nactN && dN[wi] >= 2) {
                    int cb = h * 4;
                    float cw[4];
                    #pragma unroll
                    for (int u = 0; u < 4; ++u) {
                        float fv = sm[SM_RASH2 + wi * 24 + 0  + cb + u];
                        float iv = sm[SM_RASH2 + wi * 24 + 8  + cb + u];
                        float gv = sm[SM_RASH2 + wi * 24 + 16 + cb + u];
                        float cs = sm[SM_CSSH + wi * 8 + cb + u];
                        cw[u] = fsig(fv) * cs + fsig(iv) * ftan(gv);
                        sm[SM_CWO + ((t + 1) & 1) * 32 + wi * 8 + cb + u] = cw[u];
                    }
                    *(float4*)(g_cwt + (size_t)(t + 1) * 2048 + wi * 512 + jbase + cb) =
                        make_float4(cw[0], cw[1], cw[2], cw[3]);
                }
            }
            __syncwarp();
            if (lane == 0) st_rel(myflag, seq);
        }
        // ======== barrier ========
        if (tid < GC) { while (ld_acq(&g_flag[tid * 32]) < seq) {} }
        __syncthreads();
    }
}

// ---------------- launch (4 kernels) ----------------
extern "C" void kernel_launch(void* const* d_in, const int* in_sizes, int n_in,
                              void* d_out, int out_size) {
    const float* x        = (const float*)d_in[0];
    const int*   word_ids = (const int*)  d_in[1];
    const int*   wstarts  = (const int*)  d_in[2];
    const void*  wmask    = (const void*) d_in[3];
    const float* h0       = (const float*)d_in[4];
    const float* c0       = (const float*)d_in[5];
    const float* emb      = (const float*)d_in[6];
    const float* W        = (const float*)d_in[7];
    const float* U        = (const float*)d_in[8];
    const float* b        = (const float*)d_in[9];
    const float* Wa       = (const float*)d_in[10];
    const float* Ua       = (const float*)d_in[11];
    const float* ba       = (const float*)d_in[12];
    const float* Ww       = (const float*)d_in[13];
    const float* Uw       = (const float*)d_in[14];
    const float* bw       = (const float*)d_in[15];
    float* out = (float*)d_out;

    k_prep<<<1, 1024>>>((const unsigned*)wmask, wmask, wstarts);

    dim3 gx(32, T_ / 128);
    k_gemm<<<gx, 256>>>(x, nullptr, W, b, Wa, ba, T_, D_, 3);
    dim3 gw(H3_ / 64, (T_ * WN_) / 128);
    k_gemm<<<gw, 256>>>(emb, word_ids, Ww, bw, nullptr, nullptr, T_ * WN_, 256, 2);

    static_assert(SMEM_BYTES < 220 * 1024, "smem");
    cudaFuncSetAttribute(k_seq, cudaFuncAttributeMaxDynamicSharedMemorySize,
                         SMEM_BYTES);
    k_seq<<<GC, NT, SMEM_BYTES>>>(out, U, Uw, Ua, h0, c0);
}